// round 13
// baseline (speedup 1.0000x reference)
#include <cuda_runtime.h>
#include <cuda_fp16.h>
#include <cstdint>

#define L0 32
#define DIM 288          // logical irreps dim
#define XSTR 288         // SoA row stride (si1: halves; conv: floats)
#define NRBF 8
#define HID 64
#define NPATHS 7
#define WCOLS 224        // NPATHS * L0
#define NORM 0.25f       // 1/sqrt(16)
#define NMAX 50176
#define EMAX 1048576
#define TILE_E 64
#define HSTRH 72         // h_sm row stride in halves
#define WSTRH 232        // w_sm row stride in halves

// Scratch (static device globals; no runtime allocation allowed)
__device__ __half g_si1h[(size_t)NMAX * XSTR];   // SoA si1, fp16
__device__ float  g_conv[(size_t)NMAX * XSTR];   // SoA conv accumulator, fp32
__device__ uint4  g_Bfrag16[28 * 2 * 32];        // Wr2 fp16, m16n8k16 frag order
__device__ int    g_cnt[NMAX];
__device__ int    g_off[NMAX];
__device__ int2   g_esorted[EMAX];               // dst-sorted (src,dst)

__device__ __forceinline__ unsigned pack_h2(float lo, float hi) {
    __half2 h = __floats2half2_rn(lo, hi);
    return *(unsigned*)&h;
}

// ---------------------------------------------------------------------------
// Kernel 0: dst histogram (all 512 blocks) + fp16 Wr2 fragment prep (blocks<28)
// ---------------------------------------------------------------------------
__global__ void k_histprep(const int* __restrict__ edge_index,
                           const float* __restrict__ Wr2, int E)
{
    int t = threadIdx.x;
    if (blockIdx.x < 28 && t < 64) {
        int ntg = blockIdx.x;
        int kd = t >> 5;
        int lane = t & 31;
        int col = ntg * 8 + (lane >> 2);
        int m4 = (lane & 3) * 2;
        int kb0 = (2*kd)     * 16 + m4;
        int kb1 = (2*kd + 1) * 16 + m4;
        uint4 b;
        b.x = pack_h2(Wr2[ kb0    * WCOLS + col] * NORM, Wr2[(kb0+1) * WCOLS + col] * NORM);
        b.y = pack_h2(Wr2[(kb0+8) * WCOLS + col] * NORM, Wr2[(kb0+9) * WCOLS + col] * NORM);
        b.z = pack_h2(Wr2[ kb1    * WCOLS + col] * NORM, Wr2[(kb1+1) * WCOLS + col] * NORM);
        b.w = pack_h2(Wr2[(kb1+8) * WCOLS + col] * NORM, Wr2[(kb1+9) * WCOLS + col] * NORM);
        g_Bfrag16[(ntg * 2 + kd) * 32 + lane] = b;
    }
    for (int e = blockIdx.x * blockDim.x + t; e < E; e += gridDim.x * blockDim.x)
        atomicAdd(&g_cnt[edge_index[(size_t)E + e]], 1);
}

// ---------------------------------------------------------------------------
// Kernel 1: exclusive scan of g_cnt -> g_off (single block)
// ---------------------------------------------------------------------------
__global__ void k_scan(int n)
{
    __shared__ int ps[1024];
    int t = threadIdx.x;
    int chunk = (n + 1023) >> 10;
    int lo = t * chunk, hi = lo + chunk;
    if (hi > n) hi = n;
    int s = 0;
    for (int i = lo; i < hi; i++) s += g_cnt[i];
    ps[t] = s;
    __syncthreads();
    for (int d = 1; d < 1024; d <<= 1) {
        int v = (t >= d) ? ps[t - d] : 0;
        __syncthreads();
        ps[t] += v;
        __syncthreads();
    }
    int pre = (t == 0) ? 0 : ps[t - 1];
    for (int i = lo; i < hi; i++) { g_off[i] = pre; pre += g_cnt[i]; }
}

// ---------------------------------------------------------------------------
// Kernel 2 (fused): blocks [0,nb_lin): si1 = irreps_linear(nodes) fp16 SoA +
// conv zeroing; blocks [nb_lin, nb_lin+512): scatter edges into g_esorted
// ---------------------------------------------------------------------------
__global__ void k_lin1_scatter(const float* __restrict__ x,
                               const float* __restrict__ W0,
                               const float* __restrict__ W1,
                               const float* __restrict__ W2,
                               __half* __restrict__ y,
                               float* __restrict__ convz,
                               const int* __restrict__ edge_index,
                               int N, int E, int nb_lin)
{
    if ((int)blockIdx.x >= nb_lin) {
        // ----- scatter part -----
        int bid = blockIdx.x - nb_lin;
        for (int e = bid * blockDim.x + threadIdx.x; e < E; e += 512 * blockDim.x) {
            int d = edge_index[(size_t)E + e];
            int p = atomicAdd(&g_off[d], 1);
            g_esorted[p] = make_int2(edge_index[e], d);
        }
        return;
    }

    __shared__ float W0s[1024], W1s[1024], W2s[1024];
    __shared__ float xs[8][DIM];
    int t = threadIdx.x;
    for (int i = t; i < 1024; i += blockDim.x) { W0s[i]=W0[i]; W1s[i]=W1[i]; W2s[i]=W2[i]; }
    __syncthreads();

    int wid = t >> 5, j = t & 31;
    int nwarps = (blockDim.x >> 5) * nb_lin;
    const float4 z = make_float4(0.f, 0.f, 0.f, 0.f);
    for (int n = blockIdx.x * 8 + wid; n < N; n += nwarps) {
        const float* xr = x + (size_t)n * DIM;
        #pragma unroll
        for (int q = 0; q < 9; q++) xs[wid][j + 32*q] = xr[j + 32*q];

        float4* cz = (float4*)(convz + (size_t)n * XSTR);
        cz[j] = z; cz[j + 32] = z;
        if (j < 8) cz[j + 64] = z;
        __syncwarp();

        float y0 = 0.f;
        #pragma unroll
        for (int i = 0; i < 32; i++) y0 = fmaf(xs[wid][i], W0s[i*32+j], y0);

        float y1[3] = {0.f,0.f,0.f};
        #pragma unroll
        for (int i = 0; i < 32; i++) {
            float w = W1s[i*32+j];
            #pragma unroll
            for (int c = 0; c < 3; c++) y1[c] = fmaf(xs[wid][32+3*i+c], w, y1[c]);
        }
        float y2[5] = {0.f,0.f,0.f,0.f,0.f};
        #pragma unroll
        for (int i = 0; i < 32; i++) {
            float w = W2s[i*32+j];
            #pragma unroll
            for (int c = 0; c < 5; c++) y2[c] = fmaf(xs[wid][128+5*i+c], w, y2[c]);
        }
        __half* yr = y + (size_t)n * XSTR;
        uint4 pk;
        pk.x = pack_h2(y0,    y1[0]);
        pk.y = pack_h2(y1[1], y1[2]);
        pk.z = pack_h2(y2[0], y2[1]);
        pk.w = pack_h2(y2[2], y2[3]);
        *(uint4*)(yr + j * 8) = pk;
        yr[256 + j] = __float2half_rn(y2[4]);
        __syncwarp();
    }
}

// ---------------------------------------------------------------------------
// Kernel 3: edge conv — sorted edges, fp16 MMA, register run-accumulation
// ---------------------------------------------------------------------------
__device__ __forceinline__ void mma_f16(float& d0, float& d1, float& d2, float& d3,
                                        unsigned a0, unsigned a1, unsigned a2, unsigned a3,
                                        unsigned b0, unsigned b1)
{
    asm("mma.sync.aligned.m16n8k16.row.col.f32.f16.f16.f32 "
        "{%0,%1,%2,%3}, {%4,%5,%6,%7}, {%8,%9}, {%0,%1,%2,%3};"
        : "+f"(d0), "+f"(d1), "+f"(d2), "+f"(d3)
        : "r"(a0), "r"(a1), "r"(a2), "r"(a3), "r"(b0), "r"(b1));
}

__device__ __forceinline__ void flush_red(float* __restrict__ conv, int dstn, int j,
                                          float a0, const float* a1, const float* a2)
{
    float* db = conv + (size_t)dstn * XSTR;
    asm volatile("red.global.add.v4.f32 [%0], {%1,%2,%3,%4};"
                 :: "l"(db + j*4), "f"(a0), "f"(a1[0]), "f"(a1[1]), "f"(a1[2]) : "memory");
    asm volatile("red.global.add.v4.f32 [%0], {%1,%2,%3,%4};"
                 :: "l"(db + 128 + j*4), "f"(a2[0]), "f"(a2[1]), "f"(a2[2]), "f"(a2[3]) : "memory");
    asm volatile("red.global.add.f32 [%0], %1;"
                 :: "l"(db + 256 + j), "f"(a2[4]) : "memory");
}

__global__ void __launch_bounds__(256, 3) k_edge(
    const __half* __restrict__ si1, const float* __restrict__ pos,
    const float* __restrict__ Wr1, const float* __restrict__ br1,
    float* __restrict__ conv, int E)
{
    extern __shared__ char smraw[];
    __half* h16    = (__half*)smraw;                    // 64*72*2  = 9216
    __half* w16    = (__half*)(smraw + 9216);           // 64*232*2 = 29696
    float*  rbf_sm = (float*)(smraw + 38912);           // 2048
    float*  uy_sm  = (float*)(smraw + 40960);           // 2048
    int*    src_sm = (int*)(smraw + 43008);             // 256
    int*    dst_sm = (int*)(smraw + 43264);             // 256
    float*  Wr1s   = (float*)(smraw + 43520);           // 2048
    float*  br1s   = (float*)(smraw + 45568);           // 256  -> total 45824 B

    int t = threadIdx.x;
    for (int i = t; i < NRBF * HID; i += 256) Wr1s[i] = Wr1[i];
    if (t < HID) br1s[t] = br1[t];
    __syncthreads();

    const int j  = t & 31;
    const int g  = t >> 5;
    const int e1 = t & 63;
    const int q  = t >> 6;
    const int r4 = j >> 2;
    const int c4 = j & 3;
    const int msb = g & 1;
    const int nq = g >> 1;
    const float rbf_step = 5.0f / 7.0f;

    const uint4* Bfrag = g_Bfrag16;

    int ntiles = (E + TILE_E - 1) / TILE_E;
    for (int tile = blockIdx.x; tile < ntiles; tile += gridDim.x) {
        int base = tile * TILE_E;

        // -------- phase 1a: geometry, once per edge (threads 0..63) --------
        if (t < TILE_E) {
            int eg = base + t;
            int s = 0, d = -1;
            if (eg < E) { int2 ed = g_esorted[eg]; s = ed.x; d = ed.y; }
            if (d >= 0) {
                float rx = pos[s*3+0] - pos[d*3+0];
                float ry = pos[s*3+1] - pos[d*3+1];
                float rz = pos[s*3+2] - pos[d*3+2];
                float dd = sqrtf(fmaf(rx,rx, fmaf(ry,ry, rz*rz)) + 1e-12f);
                float inv = 1.f / dd;
                float ux = rx*inv, uy = ry*inv, uz = rz*inv;
                #pragma unroll
                for (int r = 0; r < 8; r++) {
                    float dr = dd - rbf_step * (float)r;
                    rbf_sm[r*TILE_E + t] = __expf(-dr * dr);
                }
                float4* uv = (float4*)&uy_sm[t * 8];
                uv[0] = make_float4(ux, uy, uz, ux*uy);
                uv[1] = make_float4(uy*uz, (3.f*uz*uz - 1.f) * 0.2886751345948129f,
                                    ux*uz, (ux*ux - uy*uy) * 0.5f);
            } else {
                #pragma unroll
                for (int r = 0; r < 8; r++) rbf_sm[r*TILE_E + t] = 0.f;
                float4* uv = (float4*)&uy_sm[t * 8];
                uv[0] = make_float4(0.f,0.f,0.f,0.f);
                uv[1] = make_float4(0.f,0.f,0.f,0.f);
            }
            src_sm[t] = s;
            dst_sm[t] = d;
        }
        __syncthreads();

        // -------- phase 1b: hidden layer h (fp16), vectorized --------
        {
            float rbf[8];
            #pragma unroll
            for (int r = 0; r < 8; r++) rbf[r] = rbf_sm[r*TILE_E + e1];

            float a[16];
            {
                const float4* bb = (const float4*)&br1s[q*16];
                #pragma unroll
                for (int v = 0; v < 4; v++) {
                    float4 b4 = bb[v];
                    a[4*v+0]=b4.x; a[4*v+1]=b4.y; a[4*v+2]=b4.z; a[4*v+3]=b4.w;
                }
            }
            #pragma unroll
            for (int r = 0; r < 8; r++) {
                const float4* wr = (const float4*)&Wr1s[r*HID + q*16];
                float rr = rbf[r];
                #pragma unroll
                for (int v = 0; v < 4; v++) {
                    float4 w4 = wr[v];
                    a[4*v+0] = fmaf(rr, w4.x, a[4*v+0]);
                    a[4*v+1] = fmaf(rr, w4.y, a[4*v+1]);
                    a[4*v+2] = fmaf(rr, w4.z, a[4*v+2]);
                    a[4*v+3] = fmaf(rr, w4.w, a[4*v+3]);
                }
            }
            uint4 p0, p1;
            float s0 = a[0]/(1.f+__expf(-a[0])), s1 = a[1]/(1.f+__expf(-a[1]));
            float s2 = a[2]/(1.f+__expf(-a[2])), s3 = a[3]/(1.f+__expf(-a[3]));
            float s4 = a[4]/(1.f+__expf(-a[4])), s5 = a[5]/(1.f+__expf(-a[5]));
            float s6 = a[6]/(1.f+__expf(-a[6])), s7 = a[7]/(1.f+__expf(-a[7]));
            p0.x = pack_h2(s0,s1); p0.y = pack_h2(s2,s3);
            p0.z = pack_h2(s4,s5); p0.w = pack_h2(s6,s7);
            float s8 = a[8]/(1.f+__expf(-a[8])),  s9 = a[9]/(1.f+__expf(-a[9]));
            float sa = a[10]/(1.f+__expf(-a[10])), sb = a[11]/(1.f+__expf(-a[11]));
            float sc = a[12]/(1.f+__expf(-a[12])), sd = a[13]/(1.f+__expf(-a[13]));
            float se = a[14]/(1.f+__expf(-a[14])), sf = a[15]/(1.f+__expf(-a[15]));
            p1.x = pack_h2(s8,s9); p1.y = pack_h2(sa,sb);
            p1.z = pack_h2(sc,sd); p1.w = pack_h2(se,sf);
            *(uint4*)&h16[e1*HSTRH + q*16]     = p0;
            *(uint4*)&h16[e1*HSTRH + q*16 + 8] = p1;
        }
        __syncthreads();

        // -------- phase 2: w = h @ Wr2, fp16 m16n8k16, 2m x 4n split --------
        {
            float acc[2][7][4];
            #pragma unroll
            for (int mt = 0; mt < 2; mt++)
                #pragma unroll
                for (int nt = 0; nt < 7; nt++)
                    #pragma unroll
                    for (int i = 0; i < 4; i++) acc[mt][nt][i] = 0.f;

            #pragma unroll
            for (int kd = 0; kd < 2; kd++) {
                unsigned af[2][2][4];
                #pragma unroll
                for (int mt = 0; mt < 2; mt++) {
                    int arow = msb*32 + mt*16 + r4;
                    #pragma unroll
                    for (int s = 0; s < 2; s++) {
                        int ko = (2*kd + s)*16 + 2*c4;
                        af[mt][s][0] = *(unsigned*)&h16[ arow    *HSTRH + ko    ];
                        af[mt][s][1] = *(unsigned*)&h16[(arow+8)*HSTRH + ko    ];
                        af[mt][s][2] = *(unsigned*)&h16[ arow    *HSTRH + ko + 8];
                        af[mt][s][3] = *(unsigned*)&h16[(arow+8)*HSTRH + ko + 8];
                    }
                }
                #pragma unroll
                for (int nt = 0; nt < 7; nt++) {
                    int ntg = nq*7 + nt;
                    uint4 b = __ldg(&Bfrag[(ntg*2 + kd)*32 + j]);
                    #pragma unroll
                    for (int mt = 0; mt < 2; mt++) {
                        mma_f16(acc[mt][nt][0], acc[mt][nt][1], acc[mt][nt][2], acc[mt][nt][3],
                                af[mt][0][0], af[mt][0][1], af[mt][0][2], af[mt][0][3],
                                b.x, b.y);
                        mma_f16(acc[mt][nt][0], acc[mt][nt][1], acc[mt][nt][2], acc[mt][nt][3],
                                af[mt][1][0], af[mt][1][1], af[mt][1][2], af[mt][1][3],
                                b.z, b.w);
                    }
                }
            }
            #pragma unroll
            for (int mt = 0; mt < 2; mt++) {
                #pragma unroll
                for (int nt = 0; nt < 7; nt++) {
                    int col = nq*56 + nt*8 + 2*c4;
                    int row = msb*32 + mt*16 + r4;
                    *(unsigned*)&w16[ row    *WSTRH + col] = pack_h2(acc[mt][nt][0], acc[mt][nt][1]);
                    *(unsigned*)&w16[(row+8)*WSTRH + col] = pack_h2(acc[mt][nt][2], acc[mt][nt][3]);
                }
            }
        }
        __syncthreads();

        // -------- phase 3: gathers, compute, run-accumulate, red on dst change --
        {
            const int ebase = g * 8;
            int nvalid = E - base - ebase;
            nvalid = nvalid < 0 ? 0 : (nvalid > 8 ? 8 : nvalid);
            if (nvalid > 0) {
                const __half* xp = si1 + (size_t)src_sm[ebase] * XSTR;
                uint4 pA = *(const uint4*)(xp + j*8);
                unsigned short pC = *(const unsigned short*)(xp + 256 + j);

                float am0 = 0.f, am1[3] = {0.f,0.f,0.f};
                float am2[5] = {0.f,0.f,0.f,0.f,0.f};
                int cur = dst_sm[ebase];

                #pragma unroll
                for (int es = 0; es < 8; es++) {
                    if (es < nvalid) {
                        uint4 A = pA;
                        unsigned short Cc = pC;
                        if (es + 1 < nvalid) {
                            const __half* nx = si1 + (size_t)src_sm[ebase+es+1] * XSTR;
                            pA = *(const uint4*)(nx + j*8);
                            pC = *(const unsigned short*)(nx + 256 + j);
                        }
                        int e = ebase + es;
                        int d = dst_sm[e];
                        if (d != cur) {   // warp-uniform branch (sorted runs)
                            flush_red(conv, cur, j, am0, am1, am2);
                            cur = d;
                            am0 = 0.f;
                            #pragma unroll
                            for (int c = 0; c < 3; c++) am1[c] = 0.f;
                            #pragma unroll
                            for (int c = 0; c < 5; c++) am2[c] = 0.f;
                        }

                        float2 f0 = __half22float2(*(__half2*)&A.x);
                        float2 f1 = __half22float2(*(__half2*)&A.y);
                        float2 f2 = __half22float2(*(__half2*)&A.z);
                        float2 f3 = __half22float2(*(__half2*)&A.w);
                        float  C  = __half2float(*(__half*)&Cc);

                        float w[7];
                        #pragma unroll
                        for (int p = 0; p < 7; p++)
                            w[p] = __half2float(w16[e*WSTRH + p*32 + j]);

                        float4 uy0 = *(float4*)&uy_sm[e*8];
                        float4 uy1 = *(float4*)&uy_sm[e*8 + 4];

                        float x0 = f0.x;
                        float t1 = fmaf(f0.y, uy0.x, fmaf(f1.x, uy0.y, f1.y*uy0.z));
                        float t2 = f2.x*uy0.w;
                        t2 = fmaf(f2.y, uy1.x, t2);
                        t2 = fmaf(f3.x, uy1.y, t2);
                        t2 = fmaf(f3.y, uy1.z, t2);
                        t2 = fmaf(C,    uy1.w, t2);

                        am0 += fmaf(w[0], x0, fmaf(w[4], t1, w[6]*t2));
                        float a3 = w[3] * x0;
                        float a5 = w[5] * x0;
                        am1[0] += fmaf(w[1], f0.y, a3*uy0.x);
                        am1[1] += fmaf(w[1], f1.x, a3*uy0.y);
                        am1[2] += fmaf(w[1], f1.y, a3*uy0.z);
                        am2[0] += fmaf(w[2], f2.x, a5*uy0.w);
                        am2[1] += fmaf(w[2], f2.y, a5*uy1.x);
                        am2[2] += fmaf(w[2], f3.x, a5*uy1.y);
                        am2[3] += fmaf(w[2], f3.y, a5*uy1.z);
                        am2[4] += fmaf(w[2], C,    a5*uy1.w);
                    }
                }
                flush_red(conv, cur, j, am0, am1, am2);
            }
        }
        __syncthreads();
    }
}

// ---------------------------------------------------------------------------
// Kernel 4: out = gate(nodes + irreps_linear(conv))   (conv read as fp32 SoA)
// ---------------------------------------------------------------------------
__global__ void k_lin2_gate(const float* __restrict__ conv,
                            const float* __restrict__ nodes,
                            const float* __restrict__ W0,
                            const float* __restrict__ W1,
                            const float* __restrict__ W2,
                            const float* __restrict__ Wg,
                            float* __restrict__ out, int N)
{
    __shared__ float W0s[1024], W1s[1024], W2s[1024], Wgs[2048];
    __shared__ float xs[8][DIM];
    __shared__ float m0s[8][32];
    int t = threadIdx.x;
    for (int i = t; i < 1024; i += blockDim.x) { W0s[i]=W0[i]; W1s[i]=W1[i]; W2s[i]=W2[i]; }
    for (int i = t; i < 2048; i += blockDim.x) Wgs[i] = Wg[i];
    __syncthreads();

    int wid = t >> 5, j = t & 31;
    int nwarps = (blockDim.x >> 5) * gridDim.x;
    for (int n = blockIdx.x * 8 + wid; n < N; n += nwarps) {
        const float* cr = conv + (size_t)n * XSTR;
        const float* nr = nodes + (size_t)n * DIM;
        {
            float4 cA = ((const float4*)cr)[j];
            float4 cB = ((const float4*)cr)[32 + j];
            float  cC = cr[256 + j];
            xs[wid][j] = cA.x;
            xs[wid][32 + 3*j + 0] = cA.y;
            xs[wid][32 + 3*j + 1] = cA.z;
            xs[wid][32 + 3*j + 2] = cA.w;
            xs[wid][128 + 5*j + 0] = cB.x;
            xs[wid][128 + 5*j + 1] = cB.y;
            xs[wid][128 + 5*j + 2] = cB.z;
            xs[wid][128 + 5*j + 3] = cB.w;
            xs[wid][128 + 5*j + 4] = cC;
        }
        __syncwarp();

        float y0 = nr[j];
        #pragma unroll
        for (int i = 0; i < 32; i++) y0 = fmaf(xs[wid][i], W0s[i*32+j], y0);
        m0s[wid][j] = y0;
        __syncwarp();

        float ga = 0.f, gb = 0.f;
        #pragma unroll
        for (int i = 0; i < 32; i++) {
            float mi = m0s[wid][i];
            ga = fmaf(mi, Wgs[i*64 + j],      ga);
            gb = fmaf(mi, Wgs[i*64 + 32 + j], gb);
        }
        ga = 1.f / (1.f + __expf(-ga));
        gb = 1.f / (1.f + __expf(-gb));

        float y1[3];
        #pragma unroll
        for (int c = 0; c < 3; c++) y1[c] = nr[32 + 3*j + c];
        #pragma unroll
        for (int i = 0; i < 32; i++) {
            float w = W1s[i*32+j];
            #pragma unroll
            for (int c = 0; c < 3; c++) y1[c] = fmaf(xs[wid][32+3*i+c], w, y1[c]);
        }
        float y2[5];
        #pragma unroll
        for (int c = 0; c < 5; c++) y2[c] = nr[128 + 5*j + c];
        #pragma unroll
        for (int i = 0; i < 32; i++) {
            float w = W2s[i*32+j];
            #pragma unroll
            for (int c = 0; c < 5; c++) y2[c] = fmaf(xs[wid][128+5*i+c], w, y2[c]);
        }

        float* yr = out + (size_t)n * DIM;
        yr[j] = y0 / (1.f + __expf(-y0));     // silu
        #pragma unroll
        for (int c = 0; c < 3; c++) yr[32 + 3*j + c] = y1[c] * ga;
        #pragma unroll
        for (int c = 0; c < 5; c++) yr[128 + 5*j + c] = y2[c] * gb;
        __syncwarp();
    }
}

// ---------------------------------------------------------------------------
extern "C" void kernel_launch(void* const* d_in, const int* in_sizes, int n_in,
                              void* d_out, int out_size)
{
    const float* nodes = (const float*)d_in[0];
    const float* pos   = (const float*)d_in[1];
    const float* W0    = (const float*)d_in[2];
    const float* W1    = (const float*)d_in[3];
    const float* W2    = (const float*)d_in[4];
    const float* Wr1   = (const float*)d_in[5];
    const float* br1   = (const float*)d_in[6];
    const float* Wr2   = (const float*)d_in[7];
    const float* Wg    = (const float*)d_in[8];
    const int* edge_index = (const int*)d_in[10];   // int32: JAX x64 disabled
    float* out = (float*)d_out;

    int N = in_sizes[0] / DIM;
    int E = in_sizes[10] / 2;

    __half* si1p;
    float* convp;
    int* cntp;
    cudaGetSymbolAddress((void**)&si1p, g_si1h);
    cudaGetSymbolAddress((void**)&convp, g_conv);
    cudaGetSymbolAddress((void**)&cntp, g_cnt);

    int nb_lin = (N + 7) / 8;
    if (nb_lin > 2048) nb_lin = 2048;

    cudaMemsetAsync(cntp, 0, NMAX * sizeof(int));          // (memsets excluded from ncu idx)
    k_histprep<<<512, 256>>>(edge_index, Wr2, E);          // kernel 0
    k_scan<<<1, 1024>>>(N);                                // kernel 1
    k_lin1_scatter<<<nb_lin + 512, 256>>>(nodes, W0, W1, W2, si1p, convp,
                                          edge_index, N, E, nb_lin);  // kernel 2

    const int SMEM = 45824;
    cudaFuncSetAttribute(k_edge, cudaFuncAttributeMaxDynamicSharedMemorySize, SMEM);
    k_edge<<<888, 256, SMEM>>>(si1p, pos, Wr1, br1, convp, E);        // kernel 3

    k_lin2_gate<<<nb_lin, 256>>>(convp, nodes, W0, W1, W2, Wg, out, N);  // kernel 4
}

// round 14
// speedup vs baseline: 1.0752x; 1.0752x over previous
#include <cuda_runtime.h>
#include <cuda_fp16.h>
#include <cstdint>

#define L0 32
#define DIM 288          // logical irreps dim
#define XSTR 288         // SoA row stride (si1: halves; conv: floats)
#define NRBF 8
#define HID 64
#define NPATHS 7
#define WCOLS 224        // NPATHS * L0
#define NORM 0.25f       // 1/sqrt(16)
#define NMAX 50176
#define EMAX 1048576
#define TILE_E 64
#define HSTRH 72         // h_sm row stride in halves
#define WSTRH 232        // w_sm row stride in halves

// Scratch (static device globals; no runtime allocation allowed)
__device__ __half g_si1h[(size_t)NMAX * XSTR];   // SoA si1, fp16
__device__ float  g_conv[(size_t)NMAX * XSTR];   // SoA conv accumulator, fp32
__device__ uint4  g_Bfrag16[28 * 2 * 32];        // Wr2 fp16, m16n8k16 frag order
__device__ int    g_cnt[NMAX];
__device__ int    g_off[NMAX];
__device__ int2   g_esorted[EMAX];               // dst-sorted (src,dst)

// Edge-MLP first layer weights: warp-uniform reads -> constant port (LDCU)
__constant__ float c_Wr1[NRBF * HID];
__constant__ float c_br1[HID];

__device__ __forceinline__ unsigned pack_h2(float lo, float hi) {
    __half2 h = __floats2half2_rn(lo, hi);
    return *(unsigned*)&h;
}

__device__ __forceinline__ float fast_sigmoid(float a) {
    float th;
    asm("tanh.approx.f32 %0, %1;" : "=f"(th) : "f"(a * 0.5f));
    return fmaf(0.5f, th, 0.5f);
}
__device__ __forceinline__ float fast_silu(float a) {
    return a * fast_sigmoid(a);
}

// ---------------------------------------------------------------------------
// Kernel 0: dst histogram (all 512 blocks) + fp16 Wr2 fragment prep (blocks<28)
// ---------------------------------------------------------------------------
__global__ void k_histprep(const int* __restrict__ edge_index,
                           const float* __restrict__ Wr2, int E)
{
    int t = threadIdx.x;
    if (blockIdx.x < 28 && t < 64) {
        int ntg = blockIdx.x;
        int kd = t >> 5;
        int lane = t & 31;
        int col = ntg * 8 + (lane >> 2);
        int m4 = (lane & 3) * 2;
        int kb0 = (2*kd)     * 16 + m4;
        int kb1 = (2*kd + 1) * 16 + m4;
        uint4 b;
        b.x = pack_h2(Wr2[ kb0    * WCOLS + col] * NORM, Wr2[(kb0+1) * WCOLS + col] * NORM);
        b.y = pack_h2(Wr2[(kb0+8) * WCOLS + col] * NORM, Wr2[(kb0+9) * WCOLS + col] * NORM);
        b.z = pack_h2(Wr2[ kb1    * WCOLS + col] * NORM, Wr2[(kb1+1) * WCOLS + col] * NORM);
        b.w = pack_h2(Wr2[(kb1+8) * WCOLS + col] * NORM, Wr2[(kb1+9) * WCOLS + col] * NORM);
        g_Bfrag16[(ntg * 2 + kd) * 32 + lane] = b;
    }
    for (int e = blockIdx.x * blockDim.x + t; e < E; e += gridDim.x * blockDim.x)
        atomicAdd(&g_cnt[edge_index[(size_t)E + e]], 1);
}

// ---------------------------------------------------------------------------
// Kernel 1: exclusive scan of g_cnt -> g_off (single block)
// ---------------------------------------------------------------------------
__global__ void k_scan(int n)
{
    __shared__ int ps[1024];
    int t = threadIdx.x;
    int chunk = (n + 1023) >> 10;
    int lo = t * chunk, hi = lo + chunk;
    if (hi > n) hi = n;
    int s = 0;
    for (int i = lo; i < hi; i++) s += g_cnt[i];
    ps[t] = s;
    __syncthreads();
    for (int d = 1; d < 1024; d <<= 1) {
        int v = (t >= d) ? ps[t - d] : 0;
        __syncthreads();
        ps[t] += v;
        __syncthreads();
    }
    int pre = (t == 0) ? 0 : ps[t - 1];
    for (int i = lo; i < hi; i++) { g_off[i] = pre; pre += g_cnt[i]; }
}

// ---------------------------------------------------------------------------
// Kernel 2 (fused): blocks [0,nb_lin): si1 = irreps_linear(nodes) fp16 SoA +
// conv zeroing; blocks [nb_lin, nb_lin+512): scatter edges into g_esorted
// ---------------------------------------------------------------------------
__global__ void k_lin1_scatter(const float* __restrict__ x,
                               const float* __restrict__ W0,
                               const float* __restrict__ W1,
                               const float* __restrict__ W2,
                               __half* __restrict__ y,
                               float* __restrict__ convz,
                               const int* __restrict__ edge_index,
                               int N, int E, int nb_lin)
{
    if ((int)blockIdx.x >= nb_lin) {
        int bid = blockIdx.x - nb_lin;
        for (int e = bid * blockDim.x + threadIdx.x; e < E; e += 512 * blockDim.x) {
            int d = edge_index[(size_t)E + e];
            int p = atomicAdd(&g_off[d], 1);
            g_esorted[p] = make_int2(edge_index[e], d);
        }
        return;
    }

    __shared__ float W0s[1024], W1s[1024], W2s[1024];
    __shared__ float xs[8][DIM];
    int t = threadIdx.x;
    for (int i = t; i < 1024; i += blockDim.x) { W0s[i]=W0[i]; W1s[i]=W1[i]; W2s[i]=W2[i]; }
    __syncthreads();

    int wid = t >> 5, j = t & 31;
    int nwarps = (blockDim.x >> 5) * nb_lin;
    const float4 z = make_float4(0.f, 0.f, 0.f, 0.f);
    for (int n = blockIdx.x * 8 + wid; n < N; n += nwarps) {
        const float* xr = x + (size_t)n * DIM;
        #pragma unroll
        for (int q = 0; q < 9; q++) xs[wid][j + 32*q] = xr[j + 32*q];

        float4* cz = (float4*)(convz + (size_t)n * XSTR);
        cz[j] = z; cz[j + 32] = z;
        if (j < 8) cz[j + 64] = z;
        __syncwarp();

        float y0 = 0.f;
        #pragma unroll
        for (int i = 0; i < 32; i++) y0 = fmaf(xs[wid][i], W0s[i*32+j], y0);

        float y1[3] = {0.f,0.f,0.f};
        #pragma unroll
        for (int i = 0; i < 32; i++) {
            float w = W1s[i*32+j];
            #pragma unroll
            for (int c = 0; c < 3; c++) y1[c] = fmaf(xs[wid][32+3*i+c], w, y1[c]);
        }
        float y2[5] = {0.f,0.f,0.f,0.f,0.f};
        #pragma unroll
        for (int i = 0; i < 32; i++) {
            float w = W2s[i*32+j];
            #pragma unroll
            for (int c = 0; c < 5; c++) y2[c] = fmaf(xs[wid][128+5*i+c], w, y2[c]);
        }
        __half* yr = y + (size_t)n * XSTR;
        uint4 pk;
        pk.x = pack_h2(y0,    y1[0]);
        pk.y = pack_h2(y1[1], y1[2]);
        pk.z = pack_h2(y2[0], y2[1]);
        pk.w = pack_h2(y2[2], y2[3]);
        *(uint4*)(yr + j * 8) = pk;
        yr[256 + j] = __float2half_rn(y2[4]);
        __syncwarp();
    }
}

// ---------------------------------------------------------------------------
// Kernel 3: edge conv — sorted edges, fp16 MMA, register run-accumulation
// ---------------------------------------------------------------------------
__device__ __forceinline__ void mma_f16(float& d0, float& d1, float& d2, float& d3,
                                        unsigned a0, unsigned a1, unsigned a2, unsigned a3,
                                        unsigned b0, unsigned b1)
{
    asm("mma.sync.aligned.m16n8k16.row.col.f32.f16.f16.f32 "
        "{%0,%1,%2,%3}, {%4,%5,%6,%7}, {%8,%9}, {%0,%1,%2,%3};"
        : "+f"(d0), "+f"(d1), "+f"(d2), "+f"(d3)
        : "r"(a0), "r"(a1), "r"(a2), "r"(a3), "r"(b0), "r"(b1));
}

__device__ __forceinline__ void flush_red(float* __restrict__ conv, int dstn, int j,
                                          float a0, const float* a1, const float* a2)
{
    float* db = conv + (size_t)dstn * XSTR;
    asm volatile("red.global.add.v4.f32 [%0], {%1,%2,%3,%4};"
                 :: "l"(db + j*4), "f"(a0), "f"(a1[0]), "f"(a1[1]), "f"(a1[2]) : "memory");
    asm volatile("red.global.add.v4.f32 [%0], {%1,%2,%3,%4};"
                 :: "l"(db + 128 + j*4), "f"(a2[0]), "f"(a2[1]), "f"(a2[2]), "f"(a2[3]) : "memory");
    asm volatile("red.global.add.f32 [%0], %1;"
                 :: "l"(db + 256 + j), "f"(a2[4]) : "memory");
}

__global__ void __launch_bounds__(256, 3) k_edge(
    const __half* __restrict__ si1, const float* __restrict__ pos,
    float* __restrict__ conv, int E)
{
    extern __shared__ char smraw[];
    __half* h16    = (__half*)smraw;                    // 64*72*2  = 9216
    __half* w16    = (__half*)(smraw + 9216);           // 64*232*2 = 29696
    float*  rbf_sm = (float*)(smraw + 38912);           // 2048
    float*  uy_sm  = (float*)(smraw + 40960);           // 2048
    int*    src_sm = (int*)(smraw + 43008);             // 256
    int*    dst_sm = (int*)(smraw + 43264);             // 256 -> total 43520 B

    int t = threadIdx.x;

    const int j  = t & 31;
    const int g  = t >> 5;
    const int e1 = t & 63;
    const int q  = t >> 6;
    const int r4 = j >> 2;
    const int c4 = j & 3;
    const int msb = g & 1;
    const int nq = g >> 1;
    const float rbf_step = 5.0f / 7.0f;

    const uint4* Bfrag = g_Bfrag16;

    int ntiles = (E + TILE_E - 1) / TILE_E;
    for (int tile = blockIdx.x; tile < ntiles; tile += gridDim.x) {
        int base = tile * TILE_E;

        // -------- phase 1a: geometry, once per edge (threads 0..63) --------
        if (t < TILE_E) {
            int eg = base + t;
            int s = 0, d = -1;
            if (eg < E) { int2 ed = g_esorted[eg]; s = ed.x; d = ed.y; }
            if (d >= 0) {
                float rx = pos[s*3+0] - pos[d*3+0];
                float ry = pos[s*3+1] - pos[d*3+1];
                float rz = pos[s*3+2] - pos[d*3+2];
                float dd = sqrtf(fmaf(rx,rx, fmaf(ry,ry, rz*rz)) + 1e-12f);
                float inv = 1.f / dd;
                float ux = rx*inv, uy = ry*inv, uz = rz*inv;
                #pragma unroll
                for (int r = 0; r < 8; r++) {
                    float dr = dd - rbf_step * (float)r;
                    rbf_sm[r*TILE_E + t] = __expf(-dr * dr);
                }
                float4* uv = (float4*)&uy_sm[t * 8];
                uv[0] = make_float4(ux, uy, uz, ux*uy);
                uv[1] = make_float4(uy*uz, (3.f*uz*uz - 1.f) * 0.2886751345948129f,
                                    ux*uz, (ux*ux - uy*uy) * 0.5f);
            } else {
                #pragma unroll
                for (int r = 0; r < 8; r++) rbf_sm[r*TILE_E + t] = 0.f;
                float4* uv = (float4*)&uy_sm[t * 8];
                uv[0] = make_float4(0.f,0.f,0.f,0.f);
                uv[1] = make_float4(0.f,0.f,0.f,0.f);
            }
            src_sm[t] = s;
            dst_sm[t] = d;
        }
        __syncthreads();

        // -------- phase 1b: hidden layer h (fp16); Wr1/br1 via constant port ---
        {
            float rbf[8];
            #pragma unroll
            for (int r = 0; r < 8; r++) rbf[r] = rbf_sm[r*TILE_E + e1];

            float a[16];
            {
                const float4* bb = (const float4*)&c_br1[q*16];
                #pragma unroll
                for (int v = 0; v < 4; v++) {
                    float4 b4 = bb[v];
                    a[4*v+0]=b4.x; a[4*v+1]=b4.y; a[4*v+2]=b4.z; a[4*v+3]=b4.w;
                }
            }
            #pragma unroll
            for (int r = 0; r < 8; r++) {
                const float4* wr = (const float4*)&c_Wr1[r*HID + q*16];
                float rr = rbf[r];
                #pragma unroll
                for (int v = 0; v < 4; v++) {
                    float4 w4 = wr[v];
                    a[4*v+0] = fmaf(rr, w4.x, a[4*v+0]);
                    a[4*v+1] = fmaf(rr, w4.y, a[4*v+1]);
                    a[4*v+2] = fmaf(rr, w4.z, a[4*v+2]);
                    a[4*v+3] = fmaf(rr, w4.w, a[4*v+3]);
                }
            }
            // silu via tanh.approx (1 MUFU instead of EX2+RCP)
            uint4 p0, p1;
            p0.x = pack_h2(fast_silu(a[0]),  fast_silu(a[1]));
            p0.y = pack_h2(fast_silu(a[2]),  fast_silu(a[3]));
            p0.z = pack_h2(fast_silu(a[4]),  fast_silu(a[5]));
            p0.w = pack_h2(fast_silu(a[6]),  fast_silu(a[7]));
            p1.x = pack_h2(fast_silu(a[8]),  fast_silu(a[9]));
            p1.y = pack_h2(fast_silu(a[10]), fast_silu(a[11]));
            p1.z = pack_h2(fast_silu(a[12]), fast_silu(a[13]));
            p1.w = pack_h2(fast_silu(a[14]), fast_silu(a[15]));
            *(uint4*)&h16[e1*HSTRH + q*16]     = p0;
            *(uint4*)&h16[e1*HSTRH + q*16 + 8] = p1;
        }
        __syncthreads();

        // -------- phase 2: w = h @ Wr2, fp16 m16n8k16, 2m x 4n split --------
        {
            float acc[2][7][4];
            #pragma unroll
            for (int mt = 0; mt < 2; mt++)
                #pragma unroll
                for (int nt = 0; nt < 7; nt++)
                    #pragma unroll
                    for (int i = 0; i < 4; i++) acc[mt][nt][i] = 0.f;

            #pragma unroll
            for (int kd = 0; kd < 2; kd++) {
                unsigned af[2][2][4];
                #pragma unroll
                for (int mt = 0; mt < 2; mt++) {
                    int arow = msb*32 + mt*16 + r4;
                    #pragma unroll
                    for (int s = 0; s < 2; s++) {
                        int ko = (2*kd + s)*16 + 2*c4;
                        af[mt][s][0] = *(unsigned*)&h16[ arow    *HSTRH + ko    ];
                        af[mt][s][1] = *(unsigned*)&h16[(arow+8)*HSTRH + ko    ];
                        af[mt][s][2] = *(unsigned*)&h16[ arow    *HSTRH + ko + 8];
                        af[mt][s][3] = *(unsigned*)&h16[(arow+8)*HSTRH + ko + 8];
                    }
                }
                #pragma unroll
                for (int nt = 0; nt < 7; nt++) {
                    int ntg = nq*7 + nt;
                    uint4 b = __ldg(&Bfrag[(ntg*2 + kd)*32 + j]);
                    #pragma unroll
                    for (int mt = 0; mt < 2; mt++) {
                        mma_f16(acc[mt][nt][0], acc[mt][nt][1], acc[mt][nt][2], acc[mt][nt][3],
                                af[mt][0][0], af[mt][0][1], af[mt][0][2], af[mt][0][3],
                                b.x, b.y);
                        mma_f16(acc[mt][nt][0], acc[mt][nt][1], acc[mt][nt][2], acc[mt][nt][3],
                                af[mt][1][0], af[mt][1][1], af[mt][1][2], af[mt][1][3],
                                b.z, b.w);
                    }
                }
            }
            #pragma unroll
            for (int mt = 0; mt < 2; mt++) {
                #pragma unroll
                for (int nt = 0; nt < 7; nt++) {
                    int col = nq*56 + nt*8 + 2*c4;
                    int row = msb*32 + mt*16 + r4;
                    *(unsigned*)&w16[ row    *WSTRH + col] = pack_h2(acc[mt][nt][0], acc[mt][nt][1]);
                    *(unsigned*)&w16[(row+8)*WSTRH + col] = pack_h2(acc[mt][nt][2], acc[mt][nt][3]);
                }
            }
        }
        __syncthreads();

        // -------- phase 3: gathers, compute, run-accumulate, red on dst change --
        {
            const int ebase = g * 8;
            int nvalid = E - base - ebase;
            nvalid = nvalid < 0 ? 0 : (nvalid > 8 ? 8 : nvalid);
            if (nvalid > 0) {
                const __half* xp = si1 + (size_t)src_sm[ebase] * XSTR;
                uint4 pA = *(const uint4*)(xp + j*8);
                unsigned short pC = *(const unsigned short*)(xp + 256 + j);

                float am0 = 0.f, am1[3] = {0.f,0.f,0.f};
                float am2[5] = {0.f,0.f,0.f,0.f,0.f};
                int cur = dst_sm[ebase];

                #pragma unroll
                for (int es = 0; es < 8; es++) {
                    if (es < nvalid) {
                        uint4 A = pA;
                        unsigned short Cc = pC;
                        if (es + 1 < nvalid) {
                            const __half* nx = si1 + (size_t)src_sm[ebase+es+1] * XSTR;
                            pA = *(const uint4*)(nx + j*8);
                            pC = *(const unsigned short*)(nx + 256 + j);
                        }
                        int e = ebase + es;
                        int d = dst_sm[e];
                        if (d != cur) {   // warp-uniform branch (sorted runs)
                            flush_red(conv, cur, j, am0, am1, am2);
                            cur = d;
                            am0 = 0.f;
                            #pragma unroll
                            for (int c = 0; c < 3; c++) am1[c] = 0.f;
                            #pragma unroll
                            for (int c = 0; c < 5; c++) am2[c] = 0.f;
                        }

                        float2 f0 = __half22float2(*(__half2*)&A.x);
                        float2 f1 = __half22float2(*(__half2*)&A.y);
                        float2 f2 = __half22float2(*(__half2*)&A.z);
                        float2 f3 = __half22float2(*(__half2*)&A.w);
                        float  C  = __half2float(*(__half*)&Cc);

                        float w[7];
                        #pragma unroll
                        for (int p = 0; p < 7; p++)
                            w[p] = __half2float(w16[e*WSTRH + p*32 + j]);

                        float4 uy0 = *(float4*)&uy_sm[e*8];
                        float4 uy1 = *(float4*)&uy_sm[e*8 + 4];

                        float x0 = f0.x;
                        float t1 = fmaf(f0.y, uy0.x, fmaf(f1.x, uy0.y, f1.y*uy0.z));
                        float t2 = f2.x*uy0.w;
                        t2 = fmaf(f2.y, uy1.x, t2);
                        t2 = fmaf(f3.x, uy1.y, t2);
                        t2 = fmaf(f3.y, uy1.z, t2);
                        t2 = fmaf(C,    uy1.w, t2);

                        am0 += fmaf(w[0], x0, fmaf(w[4], t1, w[6]*t2));
                        float a3 = w[3] * x0;
                        float a5 = w[5] * x0;
                        am1[0] += fmaf(w[1], f0.y, a3*uy0.x);
                        am1[1] += fmaf(w[1], f1.x, a3*uy0.y);
                        am1[2] += fmaf(w[1], f1.y, a3*uy0.z);
                        am2[0] += fmaf(w[2], f2.x, a5*uy0.w);
                        am2[1] += fmaf(w[2], f2.y, a5*uy1.x);
                        am2[2] += fmaf(w[2], f3.x, a5*uy1.y);
                        am2[3] += fmaf(w[2], f3.y, a5*uy1.z);
                        am2[4] += fmaf(w[2], C,    a5*uy1.w);
                    }
                }
                flush_red(conv, cur, j, am0, am1, am2);
            }
        }
        __syncthreads();
    }
}

// ---------------------------------------------------------------------------
// Kernel 4: out = gate(nodes + irreps_linear(conv))   (conv read as fp32 SoA)
// ---------------------------------------------------------------------------
__global__ void k_lin2_gate(const float* __restrict__ conv,
                            const float* __restrict__ nodes,
                            const float* __restrict__ W0,
                            const float* __restrict__ W1,
                            const float* __restrict__ W2,
                            const float* __restrict__ Wg,
                            float* __restrict__ out, int N)
{
    __shared__ float W0s[1024], W1s[1024], W2s[1024], Wgs[2048];
    __shared__ float xs[8][DIM];
    __shared__ float m0s[8][32];
    int t = threadIdx.x;
    for (int i = t; i < 1024; i += blockDim.x) { W0s[i]=W0[i]; W1s[i]=W1[i]; W2s[i]=W2[i]; }
    for (int i = t; i < 2048; i += blockDim.x) Wgs[i] = Wg[i];
    __syncthreads();

    int wid = t >> 5, j = t & 31;
    int nwarps = (blockDim.x >> 5) * gridDim.x;
    for (int n = blockIdx.x * 8 + wid; n < N; n += nwarps) {
        const float* cr = conv + (size_t)n * XSTR;
        const float* nr = nodes + (size_t)n * DIM;
        {
            float4 cA = ((const float4*)cr)[j];
            float4 cB = ((const float4*)cr)[32 + j];
            float  cC = cr[256 + j];
            xs[wid][j] = cA.x;
            xs[wid][32 + 3*j + 0] = cA.y;
            xs[wid][32 + 3*j + 1] = cA.z;
            xs[wid][32 + 3*j + 2] = cA.w;
            xs[wid][128 + 5*j + 0] = cB.x;
            xs[wid][128 + 5*j + 1] = cB.y;
            xs[wid][128 + 5*j + 2] = cB.z;
            xs[wid][128 + 5*j + 3] = cB.w;
            xs[wid][128 + 5*j + 4] = cC;
        }
        __syncwarp();

        float y0 = nr[j];
        #pragma unroll
        for (int i = 0; i < 32; i++) y0 = fmaf(xs[wid][i], W0s[i*32+j], y0);
        m0s[wid][j] = y0;
        __syncwarp();

        float ga = 0.f, gb = 0.f;
        #pragma unroll
        for (int i = 0; i < 32; i++) {
            float mi = m0s[wid][i];
            ga = fmaf(mi, Wgs[i*64 + j],      ga);
            gb = fmaf(mi, Wgs[i*64 + 32 + j], gb);
        }
        ga = fast_sigmoid(ga);
        gb = fast_sigmoid(gb);

        float y1[3];
        #pragma unroll
        for (int c = 0; c < 3; c++) y1[c] = nr[32 + 3*j + c];
        #pragma unroll
        for (int i = 0; i < 32; i++) {
            float w = W1s[i*32+j];
            #pragma unroll
            for (int c = 0; c < 3; c++) y1[c] = fmaf(xs[wid][32+3*i+c], w, y1[c]);
        }
        float y2[5];
        #pragma unroll
        for (int c = 0; c < 5; c++) y2[c] = nr[128 + 5*j + c];
        #pragma unroll
        for (int i = 0; i < 32; i++) {
            float w = W2s[i*32+j];
            #pragma unroll
            for (int c = 0; c < 5; c++) y2[c] = fmaf(xs[wid][128+5*i+c], w, y2[c]);
        }

        float* yr = out + (size_t)n * DIM;
        yr[j] = fast_silu(y0);
        #pragma unroll
        for (int c = 0; c < 3; c++) yr[32 + 3*j + c] = y1[c] * ga;
        #pragma unroll
        for (int c = 0; c < 5; c++) yr[128 + 5*j + c] = y2[c] * gb;
        __syncwarp();
    }
}

// ---------------------------------------------------------------------------
extern "C" void kernel_launch(void* const* d_in, const int* in_sizes, int n_in,
                              void* d_out, int out_size)
{
    const float* nodes = (const float*)d_in[0];
    const float* pos   = (const float*)d_in[1];
    const float* W0    = (const float*)d_in[2];
    const float* W1    = (const float*)d_in[3];
    const float* W2    = (const float*)d_in[4];
    const float* Wr1   = (const float*)d_in[5];
    const float* br1   = (const float*)d_in[6];
    const float* Wr2   = (const float*)d_in[7];
    const float* Wg    = (const float*)d_in[8];
    const int* edge_index = (const int*)d_in[10];   // int32: JAX x64 disabled
    float* out = (float*)d_out;

    int N = in_sizes[0] / DIM;
    int E = in_sizes[10] / 2;

    __half* si1p;
    float* convp;
    int* cntp;
    cudaGetSymbolAddress((void**)&si1p, g_si1h);
    cudaGetSymbolAddress((void**)&convp, g_conv);
    cudaGetSymbolAddress((void**)&cntp, g_cnt);

    int nb_lin = (N + 7) / 8;
    if (nb_lin > 2048) nb_lin = 2048;

    cudaMemsetAsync(cntp, 0, NMAX * sizeof(int));
    cudaMemcpyToSymbolAsync(c_Wr1, Wr1, NRBF * HID * sizeof(float), 0,
                            cudaMemcpyDeviceToDevice);
    cudaMemcpyToSymbolAsync(c_br1, br1, HID * sizeof(float), 0,
                            cudaMemcpyDeviceToDevice);

    k_histprep<<<512, 256>>>(edge_index, Wr2, E);          // kernel 0
    k_scan<<<1, 1024>>>(N);                                // kernel 1
    k_lin1_scatter<<<nb_lin + 512, 256>>>(nodes, W0, W1, W2, si1p, convp,
                                          edge_index, N, E, nb_lin);  // kernel 2

    const int SMEM = 43520;
    cudaFuncSetAttribute(k_edge, cudaFuncAttributeMaxDynamicSharedMemorySize, SMEM);
    k_edge<<<888, 256, SMEM>>>(si1p, pos, convp, E);       // kernel 3

    k_lin2_gate<<<nb_lin, 256>>>(convp, nodes, W0, W1, W2, Wg, out, N);  // kernel 4
}